// round 14
// baseline (speedup 1.0000x reference)
#include <cuda_runtime.h>
#include <cuda_fp16.h>
#include <stdint.h>

#define NN 100000
#define NE_MAX 2400000
#define F_HID 32
#define STRIDE 96          // max supported in-degree, multiple of 16

// ---------------- scratch (device globals; no allocations allowed) ----------
// Row NN of xsh/h1h/z is a permanent ZERO row (never written) used as the
// bucket pad target, making all gather loops branch-free.
__device__ int     g_fill[NN];              // cursor; re-zeroed by k_prep
__device__ int     g_cnt [NN];              // PADDED count (multiple of 16)
__device__ float   g_dinv[NN];
__device__ __half2 g_xsh [NN + 1];          // fp16 {dinv*x0, dinv*x1}; [NN]=0
__device__ int     g_src [NN * STRIDE];     // bucket entries = src*8
__device__ __half2 g_h1h [(NN + 1) * F_HID/2]; // fp16 scaled h1; row NN = 0
__device__ float   g_z   [NN + 1];          // fp32 scaled z; [NN]=0
#define PAD_VAL (NN * 8)

// ---------------- K1: bucket fill (8 edges / thread) + local dtype detect ----
__global__ void k_fill(const void* raw, int E) {
    __shared__ int s_is64;
    if (threadIdx.x == 0) s_is64 = 1;
    __syncthreads();
    {   // each block independently detects dtype from first 256 pairs (pure fn)
        unsigned int v = ((const unsigned int*)raw)[2 * (threadIdx.x & 255) + 1];
        if (v) s_is64 = 0;               // benign race: all writers store 0
    }
    __syncthreads();
    int is64 = s_is64;

    int e0 = (blockIdx.x * blockDim.x + threadIdx.x) * 8;
    if (e0 >= E) return;
    int s[8], d[8];
    int n = 0;
    if (is64) {
        const long long* p = (const long long*)raw;
        if (e0 + 7 < E) {
#pragma unroll
            for (int u = 0; u < 4; u++) {
                longlong2 sv = ((const longlong2*)(p + e0))[u];
                longlong2 dv = ((const longlong2*)(p + E + e0))[u];
                s[2*u] = (int)sv.x; s[2*u+1] = (int)sv.y;
                d[2*u] = (int)dv.x; d[2*u+1] = (int)dv.y;
            }
            n = 8;
        } else {
            for (int k = e0; k < E; k++) { s[n] = (int)p[k]; d[n] = (int)p[E + k]; n++; }
        }
    } else {
        const int* p = (const int*)raw;
        if (e0 + 7 < E) {
#pragma unroll
            for (int u = 0; u < 2; u++) {
                int4 sv = ((const int4*)(p + e0))[u];
                int4 dv = ((const int4*)(p + E + e0))[u];
                s[4*u] = sv.x; s[4*u+1] = sv.y; s[4*u+2] = sv.z; s[4*u+3] = sv.w;
                d[4*u] = dv.x; d[4*u+1] = dv.y; d[4*u+2] = dv.z; d[4*u+3] = dv.w;
            }
            n = 8;
        } else {
            for (int k = e0; k < E; k++) { s[n] = p[k]; d[n] = p[E + k]; n++; }
        }
    }
#pragma unroll
    for (int k = 0; k < 8; k++) {
        if (k < n) {
            int pos = atomicAdd(&g_fill[d[k]], 1);
            if (pos < STRIDE) g_src[d[k] * STRIDE + pos] = s[k] * 8;
        }
    }
}

// ---------------- K2: snapshot+pad counts, re-zero cursors, dinv, scaled x ---
__global__ void k_prep(const float* __restrict__ x) {
    int i = blockIdx.x * blockDim.x + threadIdx.x;
    if (i >= NN) return;
    int c = g_fill[i];
    g_fill[i] = 0;                       // restore invariant for next graph replay
    int real = min(c, STRIDE);
    int cntP = (real + 15) & ~15;        // pad to multiple of 16 (<= STRIDE)
    for (int j = real; j < cntP; j++) g_src[i * STRIDE + j] = PAD_VAL;
    g_cnt[i] = cntP;
    float dv = rsqrtf((float)(c + 1));   // degree uses TRUE count
    g_dinv[i] = dv;
    float2 xv = ((const float2*)x)[i];
    g_xsh[i] = __floats2half2_rn(dv * xv.x, dv * xv.y);
}

// ---------------- K3: layer-1 gather + dense 2->32 + relu (8 lanes/node) -----
__global__ void k_gather1h1(const float* __restrict__ W1,
                            const float* __restrict__ b1) {
    int warp = (blockIdx.x * blockDim.x + threadIdx.x) >> 5;
    int lane = threadIdx.x & 31;
    int g  = lane >> 3;                  // group 0..3
    int gl = lane & 7;                   // lane within group
    int node = warp * 4 + g;
    if (node >= NN) return;
    int cntP = g_cnt[node];
    const int* bucket = g_src + node * STRIDE;

    float ax0 = 0.f, ay0 = 0.f, ax1 = 0.f, ay1 = 0.f;
    for (int e = gl; e < cntP; e += 16) {       // branch-free (padded)
        float2 a = __half22float2(g_xsh[bucket[e] >> 3]);
        float2 b = __half22float2(g_xsh[bucket[e + 8] >> 3]);
        ax0 += a.x; ay0 += a.y;
        ax1 += b.x; ay1 += b.y;
    }
    float ax = ax0 + ax1, ay = ay0 + ay1;
#pragma unroll
    for (int off = 4; off > 0; off >>= 1) {
        ax += __shfl_xor_sync(0xffffffffu, ax, off, 8);
        ay += __shfl_xor_sync(0xffffffffu, ay, off, 8);
    }
    float dv = g_dinv[node];
    float2 xs = __half22float2(g_xsh[node]);        // already dinv*x
    float a0 = dv * (ax + xs.x);
    float a1 = dv * (ay + xs.y);
    float4 w0 = __ldg(&((const float4*)W1)[gl]);            // W1[0][4gl..]
    float4 w1 = __ldg(&((const float4*)(W1 + F_HID))[gl]);  // W1[1][4gl..]
    float4 bb = __ldg(&((const float4*)b1)[gl]);
    float hx = dv * fmaxf(fmaf(a0, w0.x, fmaf(a1, w1.x, bb.x)), 0.0f);
    float hy = dv * fmaxf(fmaf(a0, w0.y, fmaf(a1, w1.y, bb.y)), 0.0f);
    float hz = dv * fmaxf(fmaf(a0, w0.z, fmaf(a1, w1.z, bb.z)), 0.0f);
    float hw = dv * fmaxf(fmaf(a0, w0.w, fmaf(a1, w1.w, bb.w)), 0.0f);
    __half2 p0 = __floats2half2_rn(hx, hy);
    __half2 p1 = __floats2half2_rn(hz, hw);
    ((__half2*)(g_h1h + (size_t)node * (F_HID/2)))[2*gl]   = p0;
    ((__half2*)(g_h1h + (size_t)node * (F_HID/2)))[2*gl+1] = p1;
}

// ---------------- K4: 8 nodes/block: warp-gather + ONE mma.sync batched GEMM -
#define G2_NPB 8
__global__ void __launch_bounds__(256)
k_gather2h2z(const float* __restrict__ W2,
             const float* __restrict__ b2,
             const float* __restrict__ W3) {
    __shared__ uint32_t sW2t[32 * 20];   // W2^T [n][k] halfs, row stride 20 uints
    __shared__ uint32_t sAgg[G2_NPB * 20]; // A rows [node][k] halfs, same stride
    __shared__ float sDv[G2_NPB];
    __shared__ float sB2[F_HID];
    __shared__ float sW3[F_HID];

    int tid = threadIdx.x;
    // ---- phase 0: stage W2^T (fp16), b2, W3 ----
    {
        int k  = tid >> 3;               // 0..31
        int n0 = (tid & 7) * 4;          // 0,4,..,28
        float4 v = *(const float4*)(W2 + k * F_HID + n0);
        __half* W2th = (__half*)sW2t;
        W2th[(n0 + 0) * 40 + k] = __float2half_rn(v.x);
        W2th[(n0 + 1) * 40 + k] = __float2half_rn(v.y);
        W2th[(n0 + 2) * 40 + k] = __float2half_rn(v.z);
        W2th[(n0 + 3) * 40 + k] = __float2half_rn(v.w);
        if (tid < F_HID) { sB2[tid] = b2[tid]; sW3[tid] = W3[tid]; }
    }

    // ---- phase 1: per-warp gather (grid is exact: 12500*8 == NN) ----
    int w    = tid >> 5;
    int lane = tid & 31;
    int node = blockIdx.x * G2_NPB + w;
    int cntP = g_cnt[node];
    const int* bucket = g_src + node * STRIDE;
    int fs = lane & 7;
    int es = lane >> 3;

    const uint2* h1rows = (const uint2*)g_h1h;

    float4 acc[4];
#pragma unroll
    for (int u = 0; u < 4; u++) acc[u] = make_float4(0.f, 0.f, 0.f, 0.f);
    for (int e = es; e < cntP; e += 16) {        // branch-free (padded)
#pragma unroll
        for (int u = 0; u < 4; u++) {
            uint2 pk = h1rows[bucket[e + 4 * u] + fs];
            float2 lo = __half22float2(*(__half2*)&pk.x);
            float2 hi = __half22float2(*(__half2*)&pk.y);
            acc[u].x += lo.x; acc[u].y += lo.y;
            acc[u].z += hi.x; acc[u].w += hi.y;
        }
    }
    float4 a;
    a.x = (acc[0].x + acc[1].x) + (acc[2].x + acc[3].x);
    a.y = (acc[0].y + acc[1].y) + (acc[2].y + acc[3].y);
    a.z = (acc[0].z + acc[1].z) + (acc[2].z + acc[3].z);
    a.w = (acc[0].w + acc[1].w) + (acc[2].w + acc[3].w);
#pragma unroll
    for (int off = 8; off <= 16; off <<= 1) {
        a.x += __shfl_xor_sync(0xffffffffu, a.x, off);
        a.y += __shfl_xor_sync(0xffffffffu, a.y, off);
        a.z += __shfl_xor_sync(0xffffffffu, a.z, off);
        a.w += __shfl_xor_sync(0xffffffffu, a.w, off);
    }
    float dv = g_dinv[node];
    uint2 pks = h1rows[(size_t)node * 8 + fs];               // self term
    float2 slo = __half22float2(*(__half2*)&pks.x);
    float2 shi = __half22float2(*(__half2*)&pks.y);
    __half2 q0 = __floats2half2_rn(dv * (a.x + slo.x), dv * (a.y + slo.y));
    __half2 q1 = __floats2half2_rn(dv * (a.z + shi.x), dv * (a.w + shi.y));
    if (es == 0) {                                  // lanes 0..7 == fs
        uint2 pk;
        pk.x = *(uint32_t*)&q0;
        pk.y = *(uint32_t*)&q1;
        *(uint2*)&sAgg[w * 20 + fs * 2] = pk;
        if (fs == 0) sDv[w] = dv;
    }
    __syncthreads();

    // ---- phase 2: warp 0 does the batched GEMM for all 8 nodes ----
    if (tid < 32) {
        int r = tid >> 2;                // node-in-block / A row 0..7
        int m = tid & 3;                 // thread-in-group
        uint32_t a0k0 = sAgg[r * 20 + m];
        uint32_t a2k0 = sAgg[r * 20 + m + 4];
        uint32_t a0k1 = sAgg[r * 20 + m + 8];
        uint32_t a2k1 = sAgg[r * 20 + m + 12];
        float dvr = sDv[r];
        float zpart = 0.0f;
#pragma unroll
        for (int nt = 0; nt < 4; nt++) {
            int n = nt * 8 + r;          // B column group handled by this thread
            uint32_t b0k0 = sW2t[n * 20 + m];
            uint32_t b1k0 = sW2t[n * 20 + m + 4];
            uint32_t b0k1 = sW2t[n * 20 + m + 8];
            uint32_t b1k1 = sW2t[n * 20 + m + 12];
            float c0 = 0.f, c1 = 0.f, c2 = 0.f, c3 = 0.f;
            asm volatile(
                "mma.sync.aligned.m16n8k16.row.col.f32.f16.f16.f32 "
                "{%0,%1,%2,%3}, {%4,%5,%6,%7}, {%8,%9}, {%0,%1,%2,%3};"
                : "+f"(c0), "+f"(c1), "+f"(c2), "+f"(c3)
                : "r"(a0k0), "r"(0u), "r"(a2k0), "r"(0u), "r"(b0k0), "r"(b1k0));
            asm volatile(
                "mma.sync.aligned.m16n8k16.row.col.f32.f16.f16.f32 "
                "{%0,%1,%2,%3}, {%4,%5,%6,%7}, {%8,%9}, {%0,%1,%2,%3};"
                : "+f"(c0), "+f"(c1), "+f"(c2), "+f"(c3)
                : "r"(a0k1), "r"(0u), "r"(a2k1), "r"(0u), "r"(b0k1), "r"(b1k1));
            int j = nt * 8 + 2 * m;
            float h0 = fmaxf(sB2[j]     + c0, 0.0f);
            float h1 = fmaxf(sB2[j + 1] + c1, 0.0f);
            zpart = fmaf(h0, sW3[j], fmaf(h1, sW3[j + 1], zpart));
        }
        zpart += __shfl_xor_sync(0xffffffffu, zpart, 1);
        zpart += __shfl_xor_sync(0xffffffffu, zpart, 2);
        if (m == 0) g_z[blockIdx.x * G2_NPB + r] = dvr * zpart;
    }
}

// ---------------- K5: layer-3 gather -> out (8 lanes per node) ---------------
__global__ void k_gather3(const float* __restrict__ b3, float* __restrict__ out) {
    int warp = (blockIdx.x * blockDim.x + threadIdx.x) >> 5;
    int lane = threadIdx.x & 31;
    int g  = lane >> 3;
    int gl = lane & 7;
    int node = warp * 4 + g;
    if (node >= NN) return;
    int cntP = g_cnt[node];
    const int* bucket = g_src + node * STRIDE;

    float acc0 = 0.0f, acc1 = 0.0f;
    for (int e = gl; e < cntP; e += 16) {        // branch-free (padded)
        acc0 += g_z[bucket[e] >> 3];
        acc1 += g_z[bucket[e + 8] >> 3];
    }
    float acc = acc0 + acc1;
#pragma unroll
    for (int off = 4; off > 0; off >>= 1)
        acc += __shfl_xor_sync(0xffffffffu, acc, off, 8);
    if (gl == 0) {
        float dv = g_dinv[node];
        out[node] = __ldg(&b3[0]) + dv * (acc + g_z[node]);
    }
}

// ---------------- launch ----------------------------------------------------
extern "C" void kernel_launch(void* const* d_in, const int* in_sizes, int n_in,
                              void* d_out, int out_size) {
    const float* x  = (const float*)d_in[0];
    const void*  ei = d_in[1];
    const float* W1 = (const float*)d_in[2];
    const float* b1 = (const float*)d_in[3];
    const float* W2 = (const float*)d_in[4];
    const float* b2 = (const float*)d_in[5];
    const float* W3 = (const float*)d_in[6];
    const float* b3 = (const float*)d_in[7];
    float* out = (float*)d_out;

    int E = in_sizes[1] / 2;
    const int B = 256;
    const int nodeQuarterBlks = (NN * 8 + B - 1) / B;        // 8-lanes-per-node

    k_fill      <<<(E / 8 + B) / B, B>>>(ei, E);
    k_prep      <<<(NN + B - 1) / B, B>>>(x);
    k_gather1h1 <<<nodeQuarterBlks, B>>>(W1, b1);
    k_gather2h2z<<<NN / G2_NPB, 256>>>(W2, b2, W3);
    k_gather3   <<<nodeQuarterBlks, B>>>(b3, out);
}

// round 17
// speedup vs baseline: 1.0075x; 1.0075x over previous
#include <cuda_runtime.h>
#include <cuda_fp16.h>
#include <stdint.h>

#define NN 100000
#define NE_MAX 2400000
#define F_HID 32
#define STRIDE 96          // max supported in-degree, multiple of 8

// ---------------- scratch (device globals; no allocations allowed) ----------
// Row NN of xsh/h1f/z is a permanent ZERO row (never written) used as the
// bucket pad target, making all gather loops branch-free.
__device__ int     g_fill[NN];              // cursor; re-zeroed by k_prep
__device__ int     g_cnt [NN];              // PADDED count (multiple of 8)
__device__ float   g_dinv[NN];
__device__ __half2 g_xsh [NN + 1];          // fp16 {dinv*x0, dinv*x1}; [NN]=0
__device__ int     g_src [NN * STRIDE];     // bucket entries = src*8
__device__ __align__(16) float g_h1f[(NN + 1) * F_HID]; // fp32 scaled h1; row NN = 0
__device__ float   g_z   [NN + 1];          // fp32 scaled z; [NN]=0
#define PAD_VAL (NN * 8)

// packed f32x2 add (sm_10x); ptxas never auto-fuses scalar FADDs
__device__ __forceinline__ void fadd2(unsigned long long& acc, unsigned long long v) {
    asm("add.rn.f32x2 %0, %0, %1;" : "+l"(acc) : "l"(v));
}
__device__ __forceinline__ float2 unpk(unsigned long long v) {
    float2 r;
    asm("mov.b64 {%0, %1}, %2;" : "=f"(r.x), "=f"(r.y) : "l"(v));
    return r;
}

// ---------------- K1: bucket fill (8 edges / thread) + local dtype detect ----
__global__ void k_fill(const void* raw, int E) {
    __shared__ int s_is64;
    if (threadIdx.x == 0) s_is64 = 1;
    __syncthreads();
    {   // each block independently detects dtype from first 256 pairs (pure fn)
        unsigned int v = ((const unsigned int*)raw)[2 * (threadIdx.x & 255) + 1];
        if (v) s_is64 = 0;               // benign race: all writers store 0
    }
    __syncthreads();
    int is64 = s_is64;

    int e0 = (blockIdx.x * blockDim.x + threadIdx.x) * 8;
    if (e0 >= E) return;
    int s[8], d[8];
    int n = 0;
    if (is64) {
        const long long* p = (const long long*)raw;
        if (e0 + 7 < E) {
#pragma unroll
            for (int u = 0; u < 4; u++) {
                longlong2 sv = ((const longlong2*)(p + e0))[u];
                longlong2 dv = ((const longlong2*)(p + E + e0))[u];
                s[2*u] = (int)sv.x; s[2*u+1] = (int)sv.y;
                d[2*u] = (int)dv.x; d[2*u+1] = (int)dv.y;
            }
            n = 8;
        } else {
            for (int k = e0; k < E; k++) { s[n] = (int)p[k]; d[n] = (int)p[E + k]; n++; }
        }
    } else {
        const int* p = (const int*)raw;
        if (e0 + 7 < E) {
#pragma unroll
            for (int u = 0; u < 2; u++) {
                int4 sv = ((const int4*)(p + e0))[u];
                int4 dv = ((const int4*)(p + E + e0))[u];
                s[4*u] = sv.x; s[4*u+1] = sv.y; s[4*u+2] = sv.z; s[4*u+3] = sv.w;
                d[4*u] = dv.x; d[4*u+1] = dv.y; d[4*u+2] = dv.z; d[4*u+3] = dv.w;
            }
            n = 8;
        } else {
            for (int k = e0; k < E; k++) { s[n] = p[k]; d[n] = p[E + k]; n++; }
        }
    }
#pragma unroll
    for (int k = 0; k < 8; k++) {
        if (k < n) {
            int pos = atomicAdd(&g_fill[d[k]], 1);
            if (pos < STRIDE) g_src[d[k] * STRIDE + pos] = s[k] * 8;
        }
    }
}

// ---------------- K2: snapshot+pad counts, re-zero cursors, dinv, scaled x ---
__global__ void k_prep(const float* __restrict__ x) {
    int i = blockIdx.x * blockDim.x + threadIdx.x;
    if (i >= NN) return;
    int c = g_fill[i];
    g_fill[i] = 0;                       // restore invariant for next graph replay
    int real = min(c, STRIDE);
    int cntP = (real + 7) & ~7;          // pad to multiple of 8 (<= STRIDE)
    for (int j = real; j < cntP; j++) g_src[i * STRIDE + j] = PAD_VAL;
    g_cnt[i] = cntP;
    float dv = rsqrtf((float)(c + 1));   // degree uses TRUE count
    g_dinv[i] = dv;
    float2 xv = ((const float2*)x)[i];
    g_xsh[i] = __floats2half2_rn(dv * xv.x, dv * xv.y);
}

// ---------------- K3: layer-1 gather + dense 2->32 + relu (8 lanes/node) -----
__global__ void k_gather1h1(const float* __restrict__ W1,
                            const float* __restrict__ b1) {
    int warp = (blockIdx.x * blockDim.x + threadIdx.x) >> 5;
    int lane = threadIdx.x & 31;
    int g  = lane >> 3;                  // group 0..3
    int gl = lane & 7;                   // lane within group
    int node = warp * 4 + g;
    if (node >= NN) return;
    int cntP = g_cnt[node];
    const int* bucket = g_src + node * STRIDE;

    float ax = 0.f, ay = 0.f;
    for (int e = gl; e < cntP; e += 8) {        // branch-free (padded)
        float2 a = __half22float2(g_xsh[bucket[e] >> 3]);
        ax += a.x; ay += a.y;
    }
#pragma unroll
    for (int off = 4; off > 0; off >>= 1) {
        ax += __shfl_xor_sync(0xffffffffu, ax, off, 8);
        ay += __shfl_xor_sync(0xffffffffu, ay, off, 8);
    }
    float dv = g_dinv[node];
    float2 xs = __half22float2(g_xsh[node]);        // already dinv*x
    float a0 = dv * (ax + xs.x);
    float a1 = dv * (ay + xs.y);
    float4 w0 = __ldg(&((const float4*)W1)[gl]);            // W1[0][4gl..]
    float4 w1 = __ldg(&((const float4*)(W1 + F_HID))[gl]);  // W1[1][4gl..]
    float4 bb = __ldg(&((const float4*)b1)[gl]);
    float4 h;
    h.x = dv * fmaxf(fmaf(a0, w0.x, fmaf(a1, w1.x, bb.x)), 0.0f);
    h.y = dv * fmaxf(fmaf(a0, w0.y, fmaf(a1, w1.y, bb.y)), 0.0f);
    h.z = dv * fmaxf(fmaf(a0, w0.z, fmaf(a1, w1.z, bb.z)), 0.0f);
    h.w = dv * fmaxf(fmaf(a0, w0.w, fmaf(a1, w1.w, bb.w)), 0.0f);
    ((float4*)g_h1f)[node * 8 + gl] = h;            // 128B contiguous per node
}

// ---------------- K4: 8 nodes/block: warp-gather(fp32,f32x2) + mma GEMM ------
#define G2_NPB 8
__global__ void __launch_bounds__(256)
k_gather2h2z(const float* __restrict__ W2,
             const float* __restrict__ b2,
             const float* __restrict__ W3) {
    __shared__ uint32_t sW2t[32 * 20];   // W2^T [n][k] halfs, row stride 20 uints
    __shared__ uint32_t sAgg[G2_NPB * 20]; // A rows [node][k] halfs, same stride
    __shared__ float sDv[G2_NPB];
    __shared__ float sB2[F_HID];
    __shared__ float sW3[F_HID];

    int tid = threadIdx.x;
    // ---- phase 0: stage W2^T (fp16), b2, W3 ----
    {
        int k  = tid >> 3;               // 0..31
        int n0 = (tid & 7) * 4;          // 0,4,..,28
        float4 v = *(const float4*)(W2 + k * F_HID + n0);
        __half* W2th = (__half*)sW2t;
        W2th[(n0 + 0) * 40 + k] = __float2half_rn(v.x);
        W2th[(n0 + 1) * 40 + k] = __float2half_rn(v.y);
        W2th[(n0 + 2) * 40 + k] = __float2half_rn(v.z);
        W2th[(n0 + 3) * 40 + k] = __float2half_rn(v.w);
        if (tid < F_HID) { sB2[tid] = b2[tid]; sW3[tid] = W3[tid]; }
    }

    // ---- phase 1: per-warp gather (grid is exact: 12500*8 == NN) ----
    int w    = tid >> 5;
    int lane = tid & 31;
    int node = blockIdx.x * G2_NPB + w;
    int cntP = g_cnt[node];
    const int* bucket = g_src + node * STRIDE;
    int fs = lane & 7;                   // feature slot: 16B (float4) 0..7
    int es = lane >> 3;                  // edge slot: 0..3

    const ulonglong2* rows = (const ulonglong2*)g_h1f;  // 16B = 2 f32x2 per slot

    unsigned long long a0lo = 0, a0hi = 0, a1lo = 0, a1hi = 0;
    for (int e = es; e < cntP; e += 8) {         // branch-free (padded)
        ulonglong2 r0 = rows[bucket[e] + fs];
        ulonglong2 r1 = rows[bucket[e + 4] + fs];
        fadd2(a0lo, r0.x); fadd2(a0hi, r0.y);
        fadd2(a1lo, r1.x); fadd2(a1hi, r1.y);
    }
    float2 u0 = unpk(a0lo), u1 = unpk(a0hi), v0 = unpk(a1lo), v1 = unpk(a1hi);
    float4 a;
    a.x = u0.x + v0.x;
    a.y = u0.y + v0.y;
    a.z = u1.x + v1.x;
    a.w = u1.y + v1.y;
#pragma unroll
    for (int off = 8; off <= 16; off <<= 1) {
        a.x += __shfl_xor_sync(0xffffffffu, a.x, off);
        a.y += __shfl_xor_sync(0xffffffffu, a.y, off);
        a.z += __shfl_xor_sync(0xffffffffu, a.z, off);
        a.w += __shfl_xor_sync(0xffffffffu, a.w, off);
    }
    float dv = g_dinv[node];
    float4 sv = ((const float4*)g_h1f)[node * 8 + fs];       // self term
    __half2 q0 = __floats2half2_rn(dv * (a.x + sv.x), dv * (a.y + sv.y));
    __half2 q1 = __floats2half2_rn(dv * (a.z + sv.z), dv * (a.w + sv.w));
    if (es == 0) {                                  // lanes 0..7 == fs
        uint2 pk;
        pk.x = *(uint32_t*)&q0;
        pk.y = *(uint32_t*)&q1;
        *(uint2*)&sAgg[w * 20 + fs * 2] = pk;
        if (fs == 0) sDv[w] = dv;
    }
    __syncthreads();

    // ---- phase 2: warp 0 does the batched GEMM for all 8 nodes ----
    if (tid < 32) {
        int r = tid >> 2;                // node-in-block / A row 0..7
        int m = tid & 3;                 // thread-in-group
        uint32_t a0k0 = sAgg[r * 20 + m];
        uint32_t a2k0 = sAgg[r * 20 + m + 4];
        uint32_t a0k1 = sAgg[r * 20 + m + 8];
        uint32_t a2k1 = sAgg[r * 20 + m + 12];
        float dvr = sDv[r];
        float zpart = 0.0f;
#pragma unroll
        for (int nt = 0; nt < 4; nt++) {
            int n = nt * 8 + r;          // B column group handled by this thread
            uint32_t b0k0 = sW2t[n * 20 + m];
            uint32_t b1k0 = sW2t[n * 20 + m + 4];
            uint32_t b0k1 = sW2t[n * 20 + m + 8];
            uint32_t b1k1 = sW2t[n * 20 + m + 12];
            float c0 = 0.f, c1 = 0.f, c2 = 0.f, c3 = 0.f;
            asm volatile(
                "mma.sync.aligned.m16n8k16.row.col.f32.f16.f16.f32 "
                "{%0,%1,%2,%3}, {%4,%5,%6,%7}, {%8,%9}, {%0,%1,%2,%3};"
                : "+f"(c0), "+f"(c1), "+f"(c2), "+f"(c3)
                : "r"(a0k0), "r"(0u), "r"(a2k0), "r"(0u), "r"(b0k0), "r"(b1k0));
            asm volatile(
                "mma.sync.aligned.m16n8k16.row.col.f32.f16.f16.f32 "
                "{%0,%1,%2,%3}, {%4,%5,%6,%7}, {%8,%9}, {%0,%1,%2,%3};"
                : "+f"(c0), "+f"(c1), "+f"(c2), "+f"(c3)
                : "r"(a0k1), "r"(0u), "r"(a2k1), "r"(0u), "r"(b0k1), "r"(b1k1));
            int j = nt * 8 + 2 * m;
            float h0 = fmaxf(sB2[j]     + c0, 0.0f);
            float h1 = fmaxf(sB2[j + 1] + c1, 0.0f);
            zpart = fmaf(h0, sW3[j], fmaf(h1, sW3[j + 1], zpart));
        }
        zpart += __shfl_xor_sync(0xffffffffu, zpart, 1);
        zpart += __shfl_xor_sync(0xffffffffu, zpart, 2);
        if (m == 0) g_z[blockIdx.x * G2_NPB + r] = dvr * zpart;
    }
}

// ---------------- K5: layer-3 gather -> out (8 lanes per node) ---------------
__global__ void k_gather3(const float* __restrict__ b3, float* __restrict__ out) {
    int warp = (blockIdx.x * blockDim.x + threadIdx.x) >> 5;
    int lane = threadIdx.x & 31;
    int g  = lane >> 3;
    int gl = lane & 7;
    int node = warp * 4 + g;
    if (node >= NN) return;
    int cntP = g_cnt[node];
    const int* bucket = g_src + node * STRIDE;

    float acc = 0.0f;
    for (int e = gl; e < cntP; e += 8)           // branch-free (padded)
        acc += g_z[bucket[e] >> 3];
#pragma unroll
    for (int off = 4; off > 0; off >>= 1)
        acc += __shfl_xor_sync(0xffffffffu, acc, off, 8);
    if (gl == 0) {
        float dv = g_dinv[node];
        out[node] = __ldg(&b3[0]) + dv * (acc + g_z[node]);
    }
}

// ---------------- launch ----------------------------------------------------
extern "C" void kernel_launch(void* const* d_in, const int* in_sizes, int n_in,
                              void* d_out, int out_size) {
    const float* x  = (const float*)d_in[0];
    const void*  ei = d_in[1];
    const float* W1 = (const float*)d_in[2];
    const float* b1 = (const float*)d_in[3];
    const float* W2 = (const float*)d_in[4];
    const float* b2 = (const float*)d_in[5];
    const float* W3 = (const float*)d_in[6];
    const float* b3 = (const float*)d_in[7];
    float* out = (float*)d_out;

    int E = in_sizes[1] / 2;
    const int B = 256;
    const int nodeQuarterBlks = (NN * 8 + B - 1) / B;        // 8-lanes-per-node

    k_fill      <<<(E / 8 + B) / B, B>>>(ei, E);
    k_prep      <<<(NN + B - 1) / B, B>>>(x);
    k_gather1h1 <<<nodeQuarterBlks, B>>>(W1, b1);
    k_gather2h2z<<<NN / G2_NPB, 256>>>(W2, b2, W3);
    k_gather3   <<<nodeQuarterBlks, B>>>(b3, out);
}